// round 1
// baseline (speedup 1.0000x reference)
#include <cuda_runtime.h>

#define POOL 7
#define NUM_ROIS 300
#define IMG_H 200
#define IMG_W 200
#define IMG_C 512

// One block per (roi, py, px). 128 threads, each handles 4 channels (float4).
__global__ __launch_bounds__(128) void roi_pool_kernel(
    const float* __restrict__ img,   // [H, W, C]
    const float* __restrict__ rois,  // [NUM_ROIS, 4] (x, y, w, h) as float
    float* __restrict__ out)         // [NUM_ROIS, POOL, POOL, C]
{
    const int b = blockIdx.x;              // 0 .. NUM_ROIS*49-1
    const int roi = b / (POOL * POOL);
    const int pos = b - roi * (POOL * POOL);
    const int py = pos / POOL;
    const int px = pos - py * POOL;
    const int t = threadIdx.x;             // 0..127, channels 4t..4t+3

    // ROI geometry (replicated across threads; pure ALU, negligible)
    const int rx = (int)rois[roi * 4 + 0];
    const int ry = (int)rois[roi * 4 + 1];
    const int rw = (int)rois[roi * 4 + 2];
    const int rh = (int)rois[roi * 4 + 3];

    const int x0 = min(max(rx, 0), IMG_W - 1);
    const int y0 = min(max(ry, 0), IMG_H - 1);
    const int w  = min(max(rw, 1), IMG_W - x0);
    const int h  = min(max(rh, 1), IMG_H - y0);

    // TF1 resize (align_corners=False): src = dst * (in/out); exact fp32 division
    const float sx = (float)w / (float)POOL;
    const float sy = (float)h / (float)POOL;
    const float xs = (float)px * sx;
    const float ys = (float)py * sy;

    int ix0 = (int)floorf(xs);
    int iy0 = (int)floorf(ys);
    const float fx = xs - (float)ix0;   // frac BEFORE clamp (matches reference)
    const float fy = ys - (float)iy0;
    ix0 = min(ix0, w - 1);
    iy0 = min(iy0, h - 1);
    const int ix1 = min(ix0 + 1, w - 1);
    const int iy1 = min(iy0 + 1, h - 1);

    const long ax0 = x0 + ix0;
    const long ax1 = x0 + ix1;
    const long ay0 = y0 + iy0;
    const long ay1 = y0 + iy1;

    const int c = t * 4;
    const float4 v00 = *(const float4*)(img + (ay0 * IMG_W + ax0) * IMG_C + c);
    const float4 v01 = *(const float4*)(img + (ay0 * IMG_W + ax1) * IMG_C + c);
    const float4 v10 = *(const float4*)(img + (ay1 * IMG_W + ax0) * IMG_C + c);
    const float4 v11 = *(const float4*)(img + (ay1 * IMG_W + ax1) * IMG_C + c);

    const float gx = 1.0f - fx;
    const float gy = 1.0f - fy;

    float4 r;
    {
        float top = v00.x * gx + v01.x * fx;
        float bot = v10.x * gx + v11.x * fx;
        r.x = top * gy + bot * fy;
    }
    {
        float top = v00.y * gx + v01.y * fx;
        float bot = v10.y * gx + v11.y * fx;
        r.y = top * gy + bot * fy;
    }
    {
        float top = v00.z * gx + v01.z * fx;
        float bot = v10.z * gx + v11.z * fx;
        r.z = top * gy + bot * fy;
    }
    {
        float top = v00.w * gx + v01.w * fx;
        float bot = v10.w * gx + v11.w * fx;
        r.w = top * gy + bot * fy;
    }

    *(float4*)(out + (long)b * IMG_C + c) = r;
}

extern "C" void kernel_launch(void* const* d_in, const int* in_sizes, int n_in,
                              void* d_out, int out_size)
{
    const float* img  = (const float*)d_in[0];
    const float* rois = (const float*)d_in[1];
    float* out = (float*)d_out;

    const int nblocks = NUM_ROIS * POOL * POOL;  // 14700
    roi_pool_kernel<<<nblocks, 128>>>(img, rois, out);
}

// round 2
// speedup vs baseline: 1.0151x; 1.0151x over previous
#include <cuda_runtime.h>

#define POOL 7
#define NUM_ROIS 300
#define IMG_H 200
#define IMG_W 200
#define IMG_C 512

// One block per (roi, py). 128 threads; each thread owns 4 channels (float4)
// and iterates over all 7 px positions (fully unrolled -> MLP up to 28 loads).
__global__ __launch_bounds__(128) void roi_pool_kernel(
    const float* __restrict__ img,   // [H, W, C]
    const float* __restrict__ rois,  // [NUM_ROIS, 4] (x, y, w, h) as float
    float* __restrict__ out)         // [NUM_ROIS, POOL, POOL, C]
{
    const int b   = blockIdx.x;          // 0 .. NUM_ROIS*7-1
    const int roi = b / POOL;
    const int py  = b - roi * POOL;
    const int c   = threadIdx.x * 4;     // channel base

    // ---- ROI geometry (uniform across block; cheap) ----
    const int rx = (int)__ldg(&rois[roi * 4 + 0]);
    const int ry = (int)__ldg(&rois[roi * 4 + 1]);
    const int rw = (int)__ldg(&rois[roi * 4 + 2]);
    const int rh = (int)__ldg(&rois[roi * 4 + 3]);

    const int x0 = min(max(rx, 0), IMG_W - 1);
    const int y0 = min(max(ry, 0), IMG_H - 1);
    const int w  = min(max(rw, 1), IMG_W - x0);
    const int h  = min(max(rh, 1), IMG_H - y0);

    // TF1 resize (align_corners=False): src = dst * (in/out); exact fp32 div
    const float sx = (float)w / (float)POOL;
    const float sy = (float)h / (float)POOL;

    // ---- vertical coords (fixed for this block) ----
    const float ys = (float)py * sy;
    int iy0 = (int)floorf(ys);
    const float fy = ys - (float)iy0;    // frac BEFORE clamp (matches reference)
    iy0 = min(iy0, h - 1);
    const int iy1 = min(iy0 + 1, h - 1);
    const float gy = 1.0f - fy;

    const float* __restrict__ row0 = img + ((long)(y0 + iy0) * IMG_W) * IMG_C + c;
    const float* __restrict__ row1 = img + ((long)(y0 + iy1) * IMG_W) * IMG_C + c;

    float* __restrict__ obase = out + ((long)roi * (POOL * POOL) + py * POOL) * IMG_C + c;

    // ---- horizontal loop, fully unrolled for load batching ----
    #pragma unroll
    for (int px = 0; px < POOL; ++px) {
        const float xs = (float)px * sx;
        int ix0 = (int)floorf(xs);
        const float fx = xs - (float)ix0;
        ix0 = min(ix0, w - 1);
        const int ix1 = min(ix0 + 1, w - 1);

        const long a0 = (long)(x0 + ix0) * IMG_C;
        const long a1 = (long)(x0 + ix1) * IMG_C;

        const float4 v00 = *(const float4*)(row0 + a0);
        const float4 v01 = *(const float4*)(row0 + a1);
        const float4 v10 = *(const float4*)(row1 + a0);
        const float4 v11 = *(const float4*)(row1 + a1);

        const float gx = 1.0f - fx;

        float4 r;
        r.x = (v00.x * gx + v01.x * fx) * gy + (v10.x * gx + v11.x * fx) * fy;
        r.y = (v00.y * gx + v01.y * fx) * gy + (v10.y * gx + v11.y * fx) * fy;
        r.z = (v00.z * gx + v01.z * fx) * gy + (v10.z * gx + v11.z * fx) * fy;
        r.w = (v00.w * gx + v01.w * fx) * gy + (v10.w * gx + v11.w * fx) * fy;

        *(float4*)(obase + (long)px * IMG_C) = r;
    }
}

extern "C" void kernel_launch(void* const* d_in, const int* in_sizes, int n_in,
                              void* d_out, int out_size)
{
    const float* img  = (const float*)d_in[0];
    const float* rois = (const float*)d_in[1];
    float* out = (float*)d_out;

    const int nblocks = NUM_ROIS * POOL;  // 2100
    roi_pool_kernel<<<nblocks, 128>>>(img, rois, out);
}